// round 4
// baseline (speedup 1.0000x reference)
#include <cuda_runtime.h>
#include <cuda_bf16.h>
#include <math.h>
#include <stdint.h>

// Problem constants
#define NTOK   8192
#define DIM    1024
#define ODIM   1024
#define NEXP   8
#define TOPK   2
#define ASSIGN (NTOK*TOPK)

// GEMM tiling
#define BM 128
#define BN 256
#define BK 32
#define NSTAGE (DIM/BK)                 // 32
#define MAX_TILES (ASSIGN/BM + NEXP)    // 136
#define GEMM_THREADS 512                // 16 warps: 2 (m) x 8 (n)

// ---- smem layout (bytes) ----
// A tile: 128 rows x 32 bf16, padded stride 40 bf16 (80B); hi+lo; double buffered
#define A_STRIDE_B 80
#define A_HL       (128*A_STRIDE_B)     // 10240
#define A_BUF      (2*A_HL)             // 20480
#define A_OFF      0
// B tile: 32 rows (k) x 256 bf16 (n), padded stride 264 bf16 (528B); hi+lo; x2 buf
#define B_STRIDE_B 528
#define B_HL       (32*B_STRIDE_B)      // 16896
#define B_BUF      (2*B_HL)             // 33792
#define B_OFF      (2*A_BUF)            // 40960
#define TOK_OFF    (B_OFF + 2*B_BUF)    // 108544
#define GATE_OFF   (TOK_OFF + 512)
#define BE_OFF     (GATE_OFF + 512)
#define SMEM_TOTAL (BE_OFF + 1024)      // 110592

// ---------------- device scratch ----------------
__device__ int   g_topk_idx[ASSIGN];
__device__ float g_topk_gate[ASSIGN];
__device__ int   g_counts[NEXP];
__device__ int   g_cursor[NEXP];
__device__ int   g_tile_expert[MAX_TILES];
__device__ int   g_tile_row[MAX_TILES];
__device__ int   g_tile_rows[MAX_TILES];
__device__ int   g_num_tiles;
__device__ int   g_assign_token[ASSIGN];
__device__ float g_assign_gate[ASSIGN];
// bf16 hi/lo split operands (x: [tok][k], W: [e][k][n])
__device__ __nv_bfloat16 g_xh[NTOK*DIM];
__device__ __nv_bfloat16 g_xl[NTOK*DIM];
__device__ __nv_bfloat16 g_Wh[NEXP*DIM*ODIM];
__device__ __nv_bfloat16 g_Wl[NEXP*DIM*ODIM];

// ---------------- PTX helpers (baseline PTX only) ----------------
__device__ __forceinline__ uint32_t smem_u32(const void* p) {
    uint32_t a;
    asm("{ .reg .u64 t; cvta.to.shared.u64 t, %1; cvt.u32.u64 %0, t; }" : "=r"(a) : "l"(p));
    return a;
}
__device__ __forceinline__ void cp16(uint32_t dst, const void* src) {
    asm volatile("cp.async.cg.shared.global [%0], [%1], 16;" :: "r"(dst), "l"(src));
}
#define CP_COMMIT() asm volatile("cp.async.commit_group;" ::: "memory")
#define CP_WAIT0()  asm volatile("cp.async.wait_group 0;" ::: "memory")

__device__ __forceinline__ void ldsm_x4(uint32_t* r, uint32_t addr) {
    asm volatile("ldmatrix.sync.aligned.m8n8.x4.shared.b16 {%0,%1,%2,%3}, [%4];"
        : "=r"(r[0]), "=r"(r[1]), "=r"(r[2]), "=r"(r[3]) : "r"(addr));
}
__device__ __forceinline__ void ldsm_x4_t(uint32_t* r, uint32_t addr) {
    asm volatile("ldmatrix.sync.aligned.m8n8.x4.trans.shared.b16 {%0,%1,%2,%3}, [%4];"
        : "=r"(r[0]), "=r"(r[1]), "=r"(r[2]), "=r"(r[3]) : "r"(addr));
}
__device__ __forceinline__ void mma_bf16(float* c, const uint32_t* a, const uint32_t* b) {
    asm volatile(
        "mma.sync.aligned.m16n8k16.row.col.f32.bf16.bf16.f32 "
        "{%0,%1,%2,%3}, {%4,%5,%6,%7}, {%8,%9}, {%0,%1,%2,%3};"
        : "+f"(c[0]), "+f"(c[1]), "+f"(c[2]), "+f"(c[3])
        : "r"(a[0]), "r"(a[1]), "r"(a[2]), "r"(a[3]), "r"(b[0]), "r"(b[1]));
}

// ---------------- init: zero counters + zero output ----------------
__global__ void init_kernel(float* __restrict__ out, int out_elems)
{
    int t = blockIdx.x * blockDim.x + threadIdx.x;
    if (t < NEXP) g_counts[t] = 0;
    if (t == 0)   g_num_tiles = 0;
    int stride = gridDim.x * blockDim.x;
    float4 z = make_float4(0.f, 0.f, 0.f, 0.f);
    for (int i = t; i < out_elems / 4; i += stride)
        reinterpret_cast<float4*>(out)[i] = z;
}

// ---------------- convert x to bf16 hi/lo ----------------
__global__ void convx_kernel(const float* __restrict__ x)
{
    int i = blockIdx.x * blockDim.x + threadIdx.x;
    if (i >= NTOK * DIM / 4) return;
    float4 v = reinterpret_cast<const float4*>(x)[i];
    __nv_bfloat16 h0 = __float2bfloat16(v.x), h1 = __float2bfloat16(v.y);
    __nv_bfloat16 h2 = __float2bfloat16(v.z), h3 = __float2bfloat16(v.w);
    __nv_bfloat16 l0 = __float2bfloat16(v.x - __bfloat162float(h0));
    __nv_bfloat16 l1 = __float2bfloat16(v.y - __bfloat162float(h1));
    __nv_bfloat16 l2 = __float2bfloat16(v.z - __bfloat162float(h2));
    __nv_bfloat16 l3 = __float2bfloat16(v.w - __bfloat162float(h3));
    __nv_bfloat162* xh2 = reinterpret_cast<__nv_bfloat162*>(g_xh);
    __nv_bfloat162* xl2 = reinterpret_cast<__nv_bfloat162*>(g_xl);
    xh2[i*2+0] = __nv_bfloat162(h0, h1);
    xh2[i*2+1] = __nv_bfloat162(h2, h3);
    xl2[i*2+0] = __nv_bfloat162(l0, l1);
    xl2[i*2+1] = __nv_bfloat162(l2, l3);
}

// ---------------- convert We to bf16 hi/lo ----------------
__global__ void convw_kernel(const float* __restrict__ We)
{
    int i = blockIdx.x * blockDim.x + threadIdx.x;
    if (i >= NEXP * DIM * ODIM / 4) return;
    float4 v = reinterpret_cast<const float4*>(We)[i];
    __nv_bfloat16 h0 = __float2bfloat16(v.x), h1 = __float2bfloat16(v.y);
    __nv_bfloat16 h2 = __float2bfloat16(v.z), h3 = __float2bfloat16(v.w);
    __nv_bfloat16 l0 = __float2bfloat16(v.x - __bfloat162float(h0));
    __nv_bfloat16 l1 = __float2bfloat16(v.y - __bfloat162float(h1));
    __nv_bfloat16 l2 = __float2bfloat16(v.z - __bfloat162float(h2));
    __nv_bfloat16 l3 = __float2bfloat16(v.w - __bfloat162float(h3));
    __nv_bfloat162* wh2 = reinterpret_cast<__nv_bfloat162*>(g_Wh);
    __nv_bfloat162* wl2 = reinterpret_cast<__nv_bfloat162*>(g_Wl);
    wh2[i*2+0] = __nv_bfloat162(h0, h1);
    wh2[i*2+1] = __nv_bfloat162(h2, h3);
    wl2[i*2+0] = __nv_bfloat162(l0, l1);
    wl2[i*2+1] = __nv_bfloat162(l2, l3);
}

// ---------------- gating: split-D, x read exactly once ----------------
// 8 threads per token; thread e loads x[d] for d in [e*128,(e+1)*128) and
// accumulates partial dot products for ALL 8 experts; 3-step xor butterfly
// gives every lane all 8 logits; then the validated top-2 reduction.
__global__ void gate_kernel(const float* __restrict__ x,
                            const float* __restrict__ Wg,
                            const float* __restrict__ bg)
{
    int t = threadIdx.x;
    int e = t & 7;
    int n = blockIdx.x * 32 + (t >> 3);
    const float* xr = x + (size_t)n * DIM + e * 128;
    const float* wr = Wg + e * 128 * NEXP;

    float acc[NEXP];
    #pragma unroll
    for (int f = 0; f < NEXP; f++) acc[f] = 0.f;

    #pragma unroll 4
    for (int d = 0; d < 128; d += 4) {
        float4 xv = *reinterpret_cast<const float4*>(xr + d);
        const float* w0 = wr + (d + 0) * NEXP;
        #pragma unroll
        for (int f = 0; f < 4; f++) {
            float4 wa = *reinterpret_cast<const float4*>(w0 + f * NEXP);
            float4 wb = *reinterpret_cast<const float4*>(w0 + f * NEXP + 4);
            float xs = (f == 0) ? xv.x : (f == 1) ? xv.y : (f == 2) ? xv.z : xv.w;
            acc[0] += xs * wa.x; acc[1] += xs * wa.y;
            acc[2] += xs * wa.z; acc[3] += xs * wa.w;
            acc[4] += xs * wb.x; acc[5] += xs * wb.y;
            acc[6] += xs * wb.z; acc[7] += xs * wb.w;
        }
    }
    // butterfly-sum the 8-vector across the 8-thread group
    #pragma unroll
    for (int off = 1; off < 8; off <<= 1)
        #pragma unroll
        for (int f = 0; f < NEXP; f++)
            acc[f] += __shfl_xor_sync(0xffffffffu, acc[f], off);

    float v = acc[e] + bg[e];
    int idx = e;
    float bv = v;  int bi = idx;
    #pragma unroll
    for (int off = 4; off; off >>= 1) {
        float ov = __shfl_xor_sync(0xffffffffu, bv, off);
        int   oi = __shfl_xor_sync(0xffffffffu, bi, off);
        if (ov > bv || (ov == bv && oi < bi)) { bv = ov; bi = oi; }
    }
    float sv = (idx == bi) ? -INFINITY : v;
    int   si = idx;
    #pragma unroll
    for (int off = 4; off; off >>= 1) {
        float ov = __shfl_xor_sync(0xffffffffu, sv, off);
        int   oi = __shfl_xor_sync(0xffffffffu, si, off);
        if (ov > sv || (ov == sv && oi < si)) { sv = ov; si = oi; }
    }
    if (e == 0) {
        float w1 = 1.0f / (1.0f + expf(sv - bv));
        float w2 = 1.0f - w1;
        g_topk_idx [n * 2 + 0] = bi;
        g_topk_idx [n * 2 + 1] = si;
        g_topk_gate[n * 2 + 0] = w1;
        g_topk_gate[n * 2 + 1] = w2;
        atomicAdd(&g_counts[bi], 1);
        atomicAdd(&g_counts[si], 1);
    }
}

// ---------------- scheduler + scatter ----------------
__global__ void sched_kernel()
{
    if (threadIdx.x != 0 || blockIdx.x != 0) return;
    int off = 0, nt = 0;
    for (int e = 0; e < NEXP; e++) {
        g_cursor[e] = off;
        int c = g_counts[e];
        for (int r = 0; r < c; r += BM) {
            g_tile_expert[nt] = e;
            g_tile_row[nt]    = off + r;
            g_tile_rows[nt]   = min(BM, c - r);
            nt++;
        }
        off += c;
    }
    g_num_tiles = nt;
}

__global__ void scatter_kernel()
{
    int n = blockIdx.x * blockDim.x + threadIdx.x;
    if (n >= NTOK) return;
    #pragma unroll
    for (int k = 0; k < TOPK; k++) {
        int   e = g_topk_idx [n * 2 + k];
        float g = g_topk_gate[n * 2 + k];
        int pos = atomicAdd(&g_cursor[e], 1);
        g_assign_token[pos] = n;
        g_assign_gate[pos]  = g;
    }
}

// ---------------- HMMA grouped GEMM ----------------
__device__ __forceinline__ void load_stage(uint32_t sm, int k0, int buf,
                                           int e, int n0, const int* s_tok)
{
    int t = threadIdx.x;
    uint32_t abase = sm + A_OFF + buf * A_BUF;
    uint32_t bbase = sm + B_OFF + buf * B_BUF;
    // A: 128 rows x 32 bf16 = 512 16B-chunks; hi+lo
    #pragma unroll
    for (int c = t; c < 512; c += GEMM_THREADS) {
        int r = c >> 2, c4 = c & 3;
        int tok = s_tok[r];
        size_t off = ((size_t)tok << 10) + k0 + (c4 << 3);
        uint32_t d = abase + r * A_STRIDE_B + c4 * 16;
        cp16(d,        g_xh + off);
        cp16(d + A_HL, g_xl + off);
    }
    // B: 32 rows (k) x 256 bf16 (n) = 1024 chunks (32 per row); hi+lo
    #pragma unroll
    for (int c = t; c < 1024; c += GEMM_THREADS) {
        int kr = c >> 5, c32 = c & 31;
        size_t off = ((size_t)(e * DIM + k0 + kr) << 10) + n0 + (c32 << 3);
        uint32_t d = bbase + kr * B_STRIDE_B + c32 * 16;
        cp16(d,        g_Wh + off);
        cp16(d + B_HL, g_Wl + off);
    }
    CP_COMMIT();
}

__global__ __launch_bounds__(GEMM_THREADS, 1)
void moe_gemm_kernel(const float* __restrict__ be, float* __restrict__ out)
{
    extern __shared__ char dsm[];
    uint32_t sm = smem_u32(dsm);
    int tile = blockIdx.x;
    if (tile >= g_num_tiles) return;
    int e    = g_tile_expert[tile];
    int row0 = g_tile_row[tile];
    int rows = g_tile_rows[tile];
    int n0   = blockIdx.y * BN;
    int t    = threadIdx.x;
    int wid  = t >> 5, lane = t & 31;
    int wm   = wid & 1;          // warp m (2)
    int wn   = wid >> 1;         // warp n (8)

    int*   s_tok  = (int*)  (dsm + TOK_OFF);
    float* s_gate = (float*)(dsm + GATE_OFF);
    float* s_be   = (float*)(dsm + BE_OFF);

    if (t < BM) {
        if (t < rows) {
            s_tok [t] = g_assign_token[row0 + t];
            s_gate[t] = g_assign_gate [row0 + t];
        } else {
            s_tok [t] = 0;       // clamped; contribution killed by gate=0
            s_gate[t] = 0.f;
        }
    }
    if (t < BN) s_be[t] = be[e * ODIM + n0 + t];
    __syncthreads();

    float acc[4][4][4];
    #pragma unroll
    for (int i = 0; i < 4; i++)
        #pragma unroll
        for (int j = 0; j < 4; j++)
            #pragma unroll
            for (int q = 0; q < 4; q++) acc[i][j][q] = 0.f;

    load_stage(sm, 0, 0, e, n0, s_tok);

    #pragma unroll 1
    for (int s = 0; s < NSTAGE; s++) {
        int buf = s & 1;
        CP_WAIT0();
        __syncthreads();
        if (s + 1 < NSTAGE)
            load_stage(sm, (s + 1) * BK, buf ^ 1, e, n0, s_tok);

        uint32_t abase = sm + A_OFF + buf * A_BUF;
        uint32_t bbase = sm + B_OFF + buf * B_BUF;
        #pragma unroll
        for (int ks = 0; ks < 2; ks++) {
            uint32_t ah[4][4], al[4][4], bh[4][2], bl[4][2];
            #pragma unroll
            for (int mi = 0; mi < 4; mi++) {
                int row = wm * 64 + mi * 16 + (lane & 15);
                uint32_t addr = abase + row * A_STRIDE_B + ks * 32 + (lane >> 4) * 16;
                ldsm_x4(ah[mi], addr);
                ldsm_x4(al[mi], addr + A_HL);
            }
            #pragma unroll
            for (int np = 0; np < 2; np++) {
                int krow = ks * 16 + (lane & 15);
                int ncol = wn * 32 + np * 16 + (lane >> 4) * 8;
                uint32_t addr = bbase + krow * B_STRIDE_B + ncol * 2;
                uint32_t th[4], tl[4];
                ldsm_x4_t(th, addr);
                ldsm_x4_t(tl, addr + B_HL);
                bh[np*2][0] = th[0]; bh[np*2][1] = th[1];
                bh[np*2+1][0] = th[2]; bh[np*2+1][1] = th[3];
                bl[np*2][0] = tl[0]; bl[np*2][1] = tl[1];
                bl[np*2+1][0] = tl[2]; bl[np*2+1][1] = tl[3];
            }
            #pragma unroll
            for (int mi = 0; mi < 4; mi++)
                #pragma unroll
                for (int ni = 0; ni < 4; ni++) {
                    mma_bf16(acc[mi][ni], ah[mi], bh[ni]);
                    mma_bf16(acc[mi][ni], ah[mi], bl[ni]);
                    mma_bf16(acc[mi][ni], al[mi], bh[ni]);
                }
        }
        __syncthreads();
    }

    // epilogue
    int r_in  = lane >> 2;
    int c_in  = (lane & 3) * 2;
    #pragma unroll
    for (int mi = 0; mi < 4; mi++) {
        int rbase = wm * 64 + mi * 16 + r_in;
        int tok0 = s_tok[rbase];     float g0 = s_gate[rbase];
        int tok1 = s_tok[rbase + 8]; float g1 = s_gate[rbase + 8];
        float* o0 = out + (size_t)tok0 * ODIM + n0;
        float* o1 = out + (size_t)tok1 * ODIM + n0;
        #pragma unroll
        for (int ni = 0; ni < 4; ni++) {
            int col = wn * 32 + ni * 8 + c_in;
            float b0 = s_be[col], b1 = s_be[col + 1];
            if (g0 != 0.f) {
                atomicAdd(o0 + col,     g0 * (acc[mi][ni][0] + b0));
                atomicAdd(o0 + col + 1, g0 * (acc[mi][ni][1] + b1));
            }
            if (g1 != 0.f) {
                atomicAdd(o1 + col,     g1 * (acc[mi][ni][2] + b0));
                atomicAdd(o1 + col + 1, g1 * (acc[mi][ni][3] + b1));
            }
        }
    }
}

// ---------------- launch ----------------
extern "C" void kernel_launch(void* const* d_in, const int* in_sizes, int n_in,
                              void* d_out, int out_size)
{
    const float* x  = (const float*)d_in[0];
    const float* We = (const float*)d_in[1];
    const float* be = (const float*)d_in[2];
    const float* Wg = (const float*)d_in[3];
    const float* bg = (const float*)d_in[4];
    float* out = (float*)d_out;

    static int smem_set = 0;
    if (!smem_set) {
        cudaFuncSetAttribute(moe_gemm_kernel,
                             cudaFuncAttributeMaxDynamicSharedMemorySize, SMEM_TOTAL);
        smem_set = 1;
    }

    init_kernel<<<512, 256>>>(out, out_size);
    convx_kernel<<<(NTOK * DIM / 4 + 255) / 256, 256>>>(x);
    convw_kernel<<<(NEXP * DIM * ODIM / 4 + 255) / 256, 256>>>(We);
    gate_kernel<<<NTOK / 32, 256>>>(x, Wg, bg);
    sched_kernel<<<1, 32>>>();
    scatter_kernel<<<(NTOK + 255) / 256, 256>>>();
    dim3 g(MAX_TILES, ODIM / BN);
    moe_gemm_kernel<<<g, GEMM_THREADS, SMEM_TOTAL>>>(be, out);
}

// round 5
// speedup vs baseline: 1.8152x; 1.8152x over previous
#include <cuda_runtime.h>
#include <cuda_fp16.h>
#include <math.h>
#include <stdint.h>

// Problem constants
#define NTOK   8192
#define DIM    1024
#define ODIM   1024
#define NEXP   8
#define TOPK   2
#define ASSIGN (NTOK*TOPK)

// GEMM tiling
#define BM 128
#define BN 256
#define BK 64
#define NSTAGE (DIM/BK)                 // 16
#define MAX_TILES (ASSIGN/BM + NEXP)    // 136
#define GEMM_THREADS 256                // 8 warps: 2 (m) x 4 (n), warp tile 64x64

// ---- smem layout (bytes) ----
// A tile: 128 rows x 64 fp16 (128B) padded to 144B; double buffered
#define A_STRIDE_B 144
#define A_BUF      (128*A_STRIDE_B)     // 18432
#define A_OFF      0
// B tile: 64 rows (k) x 256 fp16 (512B) padded to 528B; double buffered
#define B_STRIDE_B 528
#define B_BUF      (64*B_STRIDE_B)      // 33792
#define B_OFF      (2*A_BUF)            // 36864
#define TOK_OFF    (B_OFF + 2*B_BUF)    // 104448
#define GATE_OFF   (TOK_OFF + 512)
#define BE_OFF     (GATE_OFF + 512)
#define SMEM_TOTAL (BE_OFF + 1024)      // 106496

// ---------------- device scratch ----------------
__device__ int   g_topk_idx[ASSIGN];
__device__ float g_topk_gate[ASSIGN];
__device__ int   g_counts[NEXP];
__device__ int   g_cursor[NEXP];
__device__ int   g_tile_expert[MAX_TILES];
__device__ int   g_tile_row[MAX_TILES];
__device__ int   g_tile_rows[MAX_TILES];
__device__ int   g_num_tiles;
__device__ int   g_assign_token[ASSIGN];
__device__ float g_assign_gate[ASSIGN];
// fp16 operands (x: [tok][k], W: [e][k][n])
__device__ __half g_xf[NTOK*DIM];
__device__ __half g_Wf[NEXP*DIM*ODIM];

// ---------------- PTX helpers (baseline PTX only) ----------------
__device__ __forceinline__ uint32_t smem_u32(const void* p) {
    uint32_t a;
    asm("{ .reg .u64 t; cvta.to.shared.u64 t, %1; cvt.u32.u64 %0, t; }" : "=r"(a) : "l"(p));
    return a;
}
__device__ __forceinline__ void cp16(uint32_t dst, const void* src) {
    asm volatile("cp.async.cg.shared.global [%0], [%1], 16;" :: "r"(dst), "l"(src));
}
#define CP_COMMIT() asm volatile("cp.async.commit_group;" ::: "memory")
#define CP_WAIT0()  asm volatile("cp.async.wait_group 0;" ::: "memory")

__device__ __forceinline__ void ldsm_x4(uint32_t* r, uint32_t addr) {
    asm volatile("ldmatrix.sync.aligned.m8n8.x4.shared.b16 {%0,%1,%2,%3}, [%4];"
        : "=r"(r[0]), "=r"(r[1]), "=r"(r[2]), "=r"(r[3]) : "r"(addr));
}
__device__ __forceinline__ void ldsm_x4_t(uint32_t* r, uint32_t addr) {
    asm volatile("ldmatrix.sync.aligned.m8n8.x4.trans.shared.b16 {%0,%1,%2,%3}, [%4];"
        : "=r"(r[0]), "=r"(r[1]), "=r"(r[2]), "=r"(r[3]) : "r"(addr));
}
__device__ __forceinline__ void mma_f16(float* c, const uint32_t* a, const uint32_t* b) {
    asm volatile(
        "mma.sync.aligned.m16n8k16.row.col.f32.f16.f16.f32 "
        "{%0,%1,%2,%3}, {%4,%5,%6,%7}, {%8,%9}, {%0,%1,%2,%3};"
        : "+f"(c[0]), "+f"(c[1]), "+f"(c[2]), "+f"(c[3])
        : "r"(a[0]), "r"(a[1]), "r"(a[2]), "r"(a[3]), "r"(b[0]), "r"(b[1]));
}

// ---------------- init: zero counters + zero output ----------------
__global__ void init_kernel(float* __restrict__ out, int out_elems)
{
    int t = blockIdx.x * blockDim.x + threadIdx.x;
    if (t < NEXP) g_counts[t] = 0;
    if (t == 0)   g_num_tiles = 0;
    int stride = gridDim.x * blockDim.x;
    float4 z = make_float4(0.f, 0.f, 0.f, 0.f);
    for (int i = t; i < out_elems / 4; i += stride)
        reinterpret_cast<float4*>(out)[i] = z;
}

// ---------------- convert x / We to fp16 ----------------
__global__ void convx_kernel(const float* __restrict__ x)
{
    int i = blockIdx.x * blockDim.x + threadIdx.x;
    if (i >= NTOK * DIM / 4) return;
    float4 v = reinterpret_cast<const float4*>(x)[i];
    __half2* o = reinterpret_cast<__half2*>(g_xf);
    o[i*2+0] = __floats2half2_rn(v.x, v.y);
    o[i*2+1] = __floats2half2_rn(v.z, v.w);
}
__global__ void convw_kernel(const float* __restrict__ We)
{
    int i = blockIdx.x * blockDim.x + threadIdx.x;
    if (i >= NEXP * DIM * ODIM / 4) return;
    float4 v = reinterpret_cast<const float4*>(We)[i];
    __half2* o = reinterpret_cast<__half2*>(g_Wf);
    o[i*2+0] = __floats2half2_rn(v.x, v.y);
    o[i*2+1] = __floats2half2_rn(v.z, v.w);
}

// ---------------- gating: R1 broadcast pattern + 8-way ILP ----------------
// 8 threads/token, thread e computes expert e's full-D logit with 8
// independent accumulator chains (breaks the FFMA latency chain).
__global__ void gate_kernel(const float* __restrict__ x,
                            const float* __restrict__ Wg,
                            const float* __restrict__ bg)
{
    int t = threadIdx.x;
    int e = t & 7;
    int n = blockIdx.x * 32 + (t >> 3);
    const float* xr = x + (size_t)n * DIM;

    float acc[8];
    #pragma unroll
    for (int u = 0; u < 8; u++) acc[u] = 0.f;

    #pragma unroll 2
    for (int d = 0; d < DIM; d += 32) {
        #pragma unroll
        for (int u = 0; u < 8; u++) {
            int dd = d + u * 4;
            float4 xv = *reinterpret_cast<const float4*>(xr + dd);
            acc[u] += xv.x * Wg[(dd + 0) * NEXP + e];
            acc[u] += xv.y * Wg[(dd + 1) * NEXP + e];
            acc[u] += xv.z * Wg[(dd + 2) * NEXP + e];
            acc[u] += xv.w * Wg[(dd + 3) * NEXP + e];
        }
    }
    float v = ((acc[0] + acc[1]) + (acc[2] + acc[3]))
            + ((acc[4] + acc[5]) + (acc[6] + acc[7])) + bg[e];

    int idx = e;
    float bv = v;  int bi = idx;
    #pragma unroll
    for (int off = 4; off; off >>= 1) {
        float ov = __shfl_xor_sync(0xffffffffu, bv, off);
        int   oi = __shfl_xor_sync(0xffffffffu, bi, off);
        if (ov > bv || (ov == bv && oi < bi)) { bv = ov; bi = oi; }
    }
    float sv = (idx == bi) ? -INFINITY : v;
    int   si = idx;
    #pragma unroll
    for (int off = 4; off; off >>= 1) {
        float ov = __shfl_xor_sync(0xffffffffu, sv, off);
        int   oi = __shfl_xor_sync(0xffffffffu, si, off);
        if (ov > sv || (ov == sv && oi < si)) { sv = ov; si = oi; }
    }
    if (e == 0) {
        float w1 = 1.0f / (1.0f + expf(sv - bv));
        float w2 = 1.0f - w1;
        g_topk_idx [n * 2 + 0] = bi;
        g_topk_idx [n * 2 + 1] = si;
        g_topk_gate[n * 2 + 0] = w1;
        g_topk_gate[n * 2 + 1] = w2;
        atomicAdd(&g_counts[bi], 1);
        atomicAdd(&g_counts[si], 1);
    }
}

// ---------------- scheduler + scatter ----------------
__global__ void sched_kernel()
{
    if (threadIdx.x != 0 || blockIdx.x != 0) return;
    int off = 0, nt = 0;
    for (int e = 0; e < NEXP; e++) {
        g_cursor[e] = off;
        int c = g_counts[e];
        for (int r = 0; r < c; r += BM) {
            g_tile_expert[nt] = e;
            g_tile_row[nt]    = off + r;
            g_tile_rows[nt]   = min(BM, c - r);
            nt++;
        }
        off += c;
    }
    g_num_tiles = nt;
}

__global__ void scatter_kernel()
{
    int n = blockIdx.x * blockDim.x + threadIdx.x;
    if (n >= NTOK) return;
    #pragma unroll
    for (int k = 0; k < TOPK; k++) {
        int   e = g_topk_idx [n * 2 + k];
        float g = g_topk_gate[n * 2 + k];
        int pos = atomicAdd(&g_cursor[e], 1);
        g_assign_token[pos] = n;
        g_assign_gate[pos]  = g;
    }
}

// ---------------- fp16 HMMA grouped GEMM ----------------
__device__ __forceinline__ void load_stage(uint32_t sm, int k0, int buf,
                                           int e, int n0, const int* s_tok)
{
    int t = threadIdx.x;
    uint32_t abase = sm + A_OFF + buf * A_BUF;
    uint32_t bbase = sm + B_OFF + buf * B_BUF;
    // A: 128 rows x 64 fp16 = 1024 16B-chunks (8/row); 4 per thread
    #pragma unroll
    for (int c = t; c < 1024; c += GEMM_THREADS) {
        int r = c >> 3, c8 = c & 7;
        int tok = s_tok[r];
        size_t off = ((size_t)tok << 10) + k0 + (c8 << 3);
        cp16(abase + r * A_STRIDE_B + c8 * 16, g_xf + off);
    }
    // B: 64 rows (k) x 256 fp16 = 2048 chunks (32/row); 8 per thread
    #pragma unroll
    for (int c = t; c < 2048; c += GEMM_THREADS) {
        int kr = c >> 5, c32 = c & 31;
        size_t off = ((size_t)(e * DIM + k0 + kr) << 10) + n0 + (c32 << 3);
        cp16(bbase + kr * B_STRIDE_B + c32 * 16, g_Wf + off);
    }
    CP_COMMIT();
}

__global__ __launch_bounds__(GEMM_THREADS)
void moe_gemm_kernel(const float* __restrict__ be, float* __restrict__ out)
{
    extern __shared__ char dsm[];
    uint32_t sm = smem_u32(dsm);
    int tile = blockIdx.x;
    if (tile >= g_num_tiles) return;
    int e    = g_tile_expert[tile];
    int row0 = g_tile_row[tile];
    int rows = g_tile_rows[tile];
    int n0   = blockIdx.y * BN;
    int t    = threadIdx.x;
    int wid  = t >> 5, lane = t & 31;
    int wm   = wid & 1;          // warp m (2)  -> 64 rows
    int wn   = wid >> 1;         // warp n (4)  -> 64 cols

    int*   s_tok  = (int*)  (dsm + TOK_OFF);
    float* s_gate = (float*)(dsm + GATE_OFF);
    float* s_be   = (float*)(dsm + BE_OFF);

    if (t < BM) {
        if (t < rows) {
            s_tok [t] = g_assign_token[row0 + t];
            s_gate[t] = g_assign_gate [row0 + t];
        } else {
            s_tok [t] = 0;       // clamped; contribution killed by gate=0
            s_gate[t] = 0.f;
        }
    }
    s_be[t] = be[e * ODIM + n0 + t];   // 256 threads cover BN=256
    __syncthreads();

    float acc[4][8][4];
    #pragma unroll
    for (int i = 0; i < 4; i++)
        #pragma unroll
        for (int j = 0; j < 8; j++)
            #pragma unroll
            for (int q = 0; q < 4; q++) acc[i][j][q] = 0.f;

    load_stage(sm, 0, 0, e, n0, s_tok);

    #pragma unroll 1
    for (int s = 0; s < NSTAGE; s++) {
        int buf = s & 1;
        CP_WAIT0();
        __syncthreads();
        if (s + 1 < NSTAGE)
            load_stage(sm, (s + 1) * BK, buf ^ 1, e, n0, s_tok);

        uint32_t abase = sm + A_OFF + buf * A_BUF;
        uint32_t bbase = sm + B_OFF + buf * B_BUF;
        #pragma unroll
        for (int ks = 0; ks < 4; ks++) {       // 4 k16 steps in BK=64
            uint32_t a[4][4], b[8][2];
            #pragma unroll
            for (int mi = 0; mi < 4; mi++) {
                int row = wm * 64 + mi * 16 + (lane & 15);
                ldsm_x4(a[mi], abase + row * A_STRIDE_B + ks * 32 + (lane >> 4) * 16);
            }
            #pragma unroll
            for (int np = 0; np < 4; np++) {   // 4 x 16-col groups = 64 cols
                int krow = ks * 16 + (lane & 15);
                int ncol = wn * 64 + np * 16 + (lane >> 4) * 8;
                uint32_t tb[4];
                ldsm_x4_t(tb, bbase + krow * B_STRIDE_B + ncol * 2);
                b[np*2][0]   = tb[0]; b[np*2][1]   = tb[1];
                b[np*2+1][0] = tb[2]; b[np*2+1][1] = tb[3];
            }
            #pragma unroll
            for (int mi = 0; mi < 4; mi++)
                #pragma unroll
                for (int ni = 0; ni < 8; ni++)
                    mma_f16(acc[mi][ni], a[mi], b[ni]);
        }
        __syncthreads();
    }

    // epilogue
    int r_in  = lane >> 2;
    int c_in  = (lane & 3) * 2;
    #pragma unroll
    for (int mi = 0; mi < 4; mi++) {
        int rbase = wm * 64 + mi * 16 + r_in;
        int tok0 = s_tok[rbase];     float g0 = s_gate[rbase];
        int tok1 = s_tok[rbase + 8]; float g1 = s_gate[rbase + 8];
        float* o0 = out + (size_t)tok0 * ODIM + n0;
        float* o1 = out + (size_t)tok1 * ODIM + n0;
        #pragma unroll
        for (int ni = 0; ni < 8; ni++) {
            int col = wn * 64 + ni * 8 + c_in;
            float b0 = s_be[col], b1 = s_be[col + 1];
            if (g0 != 0.f) {
                atomicAdd(o0 + col,     g0 * (acc[mi][ni][0] + b0));
                atomicAdd(o0 + col + 1, g0 * (acc[mi][ni][1] + b1));
            }
            if (g1 != 0.f) {
                atomicAdd(o1 + col,     g1 * (acc[mi][ni][2] + b0));
                atomicAdd(o1 + col + 1, g1 * (acc[mi][ni][3] + b1));
            }
        }
    }
}

// ---------------- launch ----------------
extern "C" void kernel_launch(void* const* d_in, const int* in_sizes, int n_in,
                              void* d_out, int out_size)
{
    const float* x  = (const float*)d_in[0];
    const float* We = (const float*)d_in[1];
    const float* be = (const float*)d_in[2];
    const float* Wg = (const float*)d_in[3];
    const float* bg = (const float*)d_in[4];
    float* out = (float*)d_out;

    static int smem_set = 0;
    if (!smem_set) {
        cudaFuncSetAttribute(moe_gemm_kernel,
                             cudaFuncAttributeMaxDynamicSharedMemorySize, SMEM_TOTAL);
        smem_set = 1;
    }

    init_kernel<<<512, 256>>>(out, out_size);
    convx_kernel<<<(NTOK * DIM / 4 + 255) / 256, 256>>>(x);
    convw_kernel<<<(NEXP * DIM * ODIM / 4 + 255) / 256, 256>>>(We);
    gate_kernel<<<NTOK / 32, 256>>>(x, Wg, bg);
    sched_kernel<<<1, 32>>>();
    scatter_kernel<<<(NTOK + 255) / 256, 256>>>();
    dim3 g(MAX_TILES, ODIM / BN);
    moe_gemm_kernel<<<g, GEMM_THREADS, SMEM_TOTAL>>>(be, out);
}